// round 8
// baseline (speedup 1.0000x reference)
#include <cuda_runtime.h>
#include <cuda_bf16.h>
#include <cstdint>

#define NF      16381
#define NBINS   84
#define KLEN    1025
#define FFTLEN  2048
#define HOP     512
#define NSAMP   8388608
#define XPAD    (NSAMP + 2048)

typedef unsigned long long ull;

__device__ __forceinline__ ull pk2(float a, float b) {
    ull r; asm("mov.b64 %0, {%1, %2};" : "=l"(r) : "f"(a), "f"(b)); return r;
}
__device__ __forceinline__ ull ffma2(ull a, ull b, ull c) {
    ull d; asm("fma.rn.f32x2 %0, %1, %2, %3;" : "=l"(d) : "l"(a), "l"(b), "l"(c)); return d;
}
__device__ __forceinline__ float2 upk2(ull v) {
    float2 f; asm("mov.b64 {%0, %1}, %2;" : "=f"(f.x), "=f"(f.y) : "l"(v)); return f;
}
__device__ __forceinline__ uint32_t smem_u32(const void* p) {
    uint32_t a; asm("{ .reg .u64 t; cvta.to.shared.u64 t, %1; cvt.u32.u64 %0, t; }" : "=r"(a) : "l"(p));
    return a;
}

// ---------------- scratch globals ----------------
#define KSPLIT 8
__device__ float2 g_part[KSPLIT][96 * FFTLEN];          // k1 partials [z][b*2048+n]
__device__ __align__(128) char g_xh8[XPAD];             // x hi bytes (qx = 128*xh + xl)
__device__ __align__(128) char g_xl8[XPAD];             // x lo bytes
#define NROW 192
__device__ __align__(128) char g_Bq[2][NROW * FFTLEN];  // [ch/cl][row][k] int8
__device__ float g_inv[NROW];                            // per-row epilogue scale

// ---------------------------------------------------------------------------
// k1: combined kernels Cmb[b,n] = (kr@wc - ki@ws, kr@ws + ki@wc)
// grid(16, 3, 8) x 256.  Thread: 4 bins x 4 n.  (unchanged from R7)
// ---------------------------------------------------------------------------
__global__ __launch_bounds__(256) void k1_combine(const float* __restrict__ kr,
                                                  const float* __restrict__ ki,
                                                  const float* __restrict__ wc,
                                                  const float* __restrict__ ws) {
    int tid = threadIdx.x;
    int nt = tid & 31, bt = tid >> 5;
    int b0 = blockIdx.y * 32 + bt * 4;
    if (b0 >= NBINS) return;
    int n0 = blockIdx.x * 128 + nt * 4;
    int z = blockIdx.z;
    int k = z * 128;
    int kend = (z == KSPLIT - 1) ? KLEN : k + 128;

    const float* krp = kr + (size_t)b0 * KLEN;
    const float* kip = ki + (size_t)b0 * KLEN;

    ull accr[4][2], acci[4][2];
#pragma unroll
    for (int i = 0; i < 4; i++)
#pragma unroll
        for (int j = 0; j < 2; j++) { accr[i][j] = 0ull; acci[i][j] = 0ull; }

#pragma unroll 4
    for (; k < kend; k++) {
        ulonglong2 c2 = *(const ulonglong2*)(wc + (size_t)k * FFTLEN + n0);
        ulonglong2 s2 = *(const ulonglong2*)(ws + (size_t)k * FFTLEN + n0);
        ull cp[2] = {c2.x, c2.y};
        ull sp[2] = {s2.x, s2.y};
#pragma unroll
        for (int i = 0; i < 4; i++) {
            float r  = __ldg(krp + (size_t)i * KLEN + k);
            float im = __ldg(kip + (size_t)i * KLEN + k);
            ull krd = pk2(r, r), kin = pk2(-im, -im), kp = pk2(im, im);
#pragma unroll
            for (int j = 0; j < 2; j++) {
                accr[i][j] = ffma2(krd, cp[j], accr[i][j]);
                accr[i][j] = ffma2(kin, sp[j], accr[i][j]);
                acci[i][j] = ffma2(krd, sp[j], acci[i][j]);
                acci[i][j] = ffma2(kp,  cp[j], acci[i][j]);
            }
        }
    }

#pragma unroll
    for (int i = 0; i < 4; i++)
#pragma unroll
        for (int j = 0; j < 2; j++) {
            float2 r = upk2(accr[i][j]);
            float2 m = upk2(acci[i][j]);
            float4 v = make_float4(r.x, m.x, r.y, m.y);
            *(float4*)&g_part[z][(size_t)(b0 + i) * FFTLEN + n0 + 2 * j] = v;
        }
}

// ---------------------------------------------------------------------------
// kx: quantize x -> 15-bit fixed point, split into int8 hi/lo.
// qx = rn(x*2048);  xh = rn(qx/128);  xl = qx - 128*xh  (|xl| <= 64)
// ---------------------------------------------------------------------------
__global__ __launch_bounds__(256) void kx_quant(const float* __restrict__ x) {
    size_t base = ((size_t)blockIdx.x * 256 + threadIdx.x) * 4;
    if (base >= XPAD) return;
    float4 v = make_float4(0.f, 0.f, 0.f, 0.f);
    if (base + 4 <= NSAMP) v = *(const float4*)(x + base);
    float vs[4] = {v.x, v.y, v.z, v.w};
    uint32_t hq = 0, lq = 0;
#pragma unroll
    for (int t = 0; t < 4; t++) {
        float xv = fminf(fmaxf(vs[t], -7.9f), 7.9f);
        int q = __float2int_rn(xv * 2048.f);
        int xh = __float2int_rn((float)q * 0.0078125f);
        int xl = q - (xh << 7);
        hq |= ((uint32_t)(xh & 0xff)) << (t * 8);
        lq |= ((uint32_t)(xl & 0xff)) << (t * 8);
    }
    *(uint32_t*)(g_xh8 + base) = hq;
    *(uint32_t*)(g_xl8 + base) = lq;
}

// ---------------------------------------------------------------------------
// k2: fold k1 partials -> per-row absmax -> quantize to int8 hi/lo pairs.
// One block per row (192). Row j: even = Cr[j/2], odd = Ci[j/2].
// ---------------------------------------------------------------------------
__global__ __launch_bounds__(256) void k2_quant() {
    int j = blockIdx.x;
    __shared__ float rowv[FFTLEN];
    __shared__ float red[256];
    int tid = threadIdx.x;
    int b = j >> 1, im = j & 1;

    float amax = 0.f;
    for (int t = tid; t < FFTLEN; t += 256) {
        float v = 0.f;
        if (j < 2 * NBINS) {
#pragma unroll
            for (int z = 0; z < KSPLIT; z++) {
                float2 p = g_part[z][(size_t)b * FFTLEN + t];
                v += im ? p.y : p.x;
            }
        }
        rowv[t] = v;
        amax = fmaxf(amax, fabsf(v));
    }
    red[tid] = amax;
    __syncthreads();
    for (int s = 128; s > 0; s >>= 1) {
        if (tid < s) red[tid] = fmaxf(red[tid], red[tid + s]);
        __syncthreads();
    }
    float absmax = red[0];
    float Sc = 16256.f / fmaxf(absmax, 1e-30f);
    if (tid == 0) g_inv[j] = absmax * (1.f / (2048.f * 16256.f));

    for (int t = tid; t < FFTLEN; t += 256) {
        int qc = __float2int_rn(rowv[t] * Sc);
        int ch = __float2int_rn((float)qc * 0.0078125f);
        int cl = qc - (ch << 7);
        g_Bq[0][(size_t)j * FFTLEN + t] = (char)ch;
        g_Bq[1][(size_t)j * FFTLEN + t] = (char)cl;
    }
}

// ---------------------------------------------------------------------------
// k3: INT8 IMMA GEMM (m16n8k32.s8), exact s32 accumulation.
//   seg0: xh*ch -> accA ; seg1: xh*cl -> accB ; seg2: xl*ch -> accB
//   value = (16384*accA + 128*accB) * rowmax/(2048*16256)
// CTA: 64 frames x 192 rows, 512 thr = 16 warps (4M x 4N), warp tile m16 x n48.
// 4-stage cp.async ring, 48/80-byte padded rows (conflict-free ldmatrix).
// ---------------------------------------------------------------------------
#define K3T 512
#define KCH 64
#define NCHSEG (FFTLEN / KCH)     // 32
#define NCHUNK (3 * NCHSEG)       // 96
#define ROWB 80                   // 64B data + 16 pad
#define CTAM 64
#define A_SM (CTAM * ROWB)        // 5120
#define B_SM (NROW * ROWB)        // 15360
#define STAGE (A_SM + B_SM)       // 20480
#define NSTAGE 4
#define K3_SMEM (NSTAGE * STAGE)  // 81920

__device__ __forceinline__ void ldsm4(uint32_t* r, uint32_t addr) {
    asm volatile("ldmatrix.sync.aligned.m8n8.x4.shared.b16 {%0,%1,%2,%3}, [%4];"
                 : "=r"(r[0]), "=r"(r[1]), "=r"(r[2]), "=r"(r[3]) : "r"(addr));
}
__device__ __forceinline__ void imma(int* d, const uint32_t* a, uint32_t b0, uint32_t b1) {
    asm volatile("mma.sync.aligned.m16n8k32.row.col.s32.s8.s8.s32 "
                 "{%0,%1,%2,%3}, {%4,%5,%6,%7}, {%8,%9}, {%0,%1,%2,%3};"
                 : "+r"(d[0]), "+r"(d[1]), "+r"(d[2]), "+r"(d[3])
                 : "r"(a[0]), "r"(a[1]), "r"(a[2]), "r"(a[3]), "r"(b0), "r"(b1));
}
__device__ __forceinline__ void cp16(uint32_t dst, const void* src) {
    asm volatile("cp.async.cg.shared.global [%0], [%1], 16;" :: "r"(dst), "l"(src));
}

__global__ __launch_bounds__(K3T, 1) void k3_cqt(float* __restrict__ out) {
    extern __shared__ __align__(16) char dsm[];
    uint32_t sb = smem_u32(dsm);

    int tid = threadIdx.x;
    int lane = tid & 31, wid = tid >> 5;
    int wm = wid & 3, wn = wid >> 2;
    int f0 = blockIdx.x * CTAM;

    auto issue = [&](int c) {
        int s = c & 3;
        int seg = c / NCHSEG;
        int n0 = (c % NCHSEG) * KCH;
        const char* xs = (seg == 2) ? g_xl8 : g_xh8;
        const char* bi = g_Bq[(seg == 1) ? 1 : 0];
        uint32_t ab = sb + s * STAGE;
        if (tid < 256) {
            int row = tid >> 2, q = tid & 3;
            cp16(ab + row * ROWB + q * 16,
                 xs + (size_t)(f0 + row) * HOP + n0 + q * 16);
        }
        uint32_t bb = ab + A_SM;
        {
            int row = tid >> 2, q = tid & 3;
            cp16(bb + row * ROWB + q * 16,
                 bi + (size_t)row * FFTLEN + n0 + q * 16);
            int row2 = row + 128;
            if (row2 < NROW)
                cp16(bb + row2 * ROWB + q * 16,
                     bi + (size_t)row2 * FFTLEN + n0 + q * 16);
        }
        asm volatile("cp.async.commit_group;" ::: "memory");
    };

    int accA[6][4], accB[6][4];
#pragma unroll
    for (int nj = 0; nj < 6; nj++)
#pragma unroll
        for (int t = 0; t < 4; t++) { accA[nj][t] = 0; accB[nj][t] = 0; }

    int lrow8 = ((lane >> 3) & 1) * 8 + (lane & 7);
    int lkh = ((lane >> 4) & 1) * 16;
    uint32_t aoff = (wm * 16 + lrow8) * ROWB + lkh;
    uint32_t boff = A_SM + (wn * 48 + lrow8) * ROWB + lkh;

    issue(0); issue(1); issue(2); issue(3);
    asm volatile("cp.async.wait_group 2;" ::: "memory");
    __syncthreads();

    for (int c = 0; c < NCHUNK; c++) {
        uint32_t ab = sb + (c & 3) * STAGE;
        bool segA = (c < NCHSEG);

#pragma unroll
        for (int h = 0; h < 2; h++) {
            uint32_t af[4], bf[3][4];
            ldsm4(af, ab + aoff + h * 32);
#pragma unroll
            for (int ni = 0; ni < 3; ni++)
                ldsm4(bf[ni], ab + boff + ni * 16 * ROWB + h * 32);
            if (segA) {
#pragma unroll
                for (int nj = 0; nj < 6; nj++)
                    imma(accA[nj], af, bf[nj >> 1][nj & 1], bf[nj >> 1][(nj & 1) + 2]);
            } else {
#pragma unroll
                for (int nj = 0; nj < 6; nj++)
                    imma(accB[nj], af, bf[nj >> 1][nj & 1], bf[nj >> 1][(nj & 1) + 2]);
            }
        }

        if (c + 4 < NCHUNK) {
            asm volatile("cp.async.wait_group 1;" ::: "memory");
            __syncthreads();
            issue(c + 4);
        } else {
            asm volatile("cp.async.wait_group 0;" ::: "memory");
            __syncthreads();
        }
    }

    // epilogue: combine terms, rescale, magnitude, store
#pragma unroll
    for (int nj = 0; nj < 6; nj++) {
        int ce = wn * 48 + nj * 8 + (lane & 3) * 2;   // even row = re, +1 = im
        int b = ce >> 1;
        if (b >= NBINS) continue;
        float invr = __ldg(&g_inv[ce]);
        float invi = __ldg(&g_inv[ce + 1]);
        int fA = f0 + wm * 16 + (lane >> 2);
        if (fA < NF) {
            float re = (16384.f * (float)accA[nj][0] + 128.f * (float)accB[nj][0]) * invr;
            float im = (16384.f * (float)accA[nj][1] + 128.f * (float)accB[nj][1]) * invi;
            out[(size_t)b * NF + fA] = sqrtf(re * re + im * im);
        }
        if (fA + 8 < NF) {
            float re = (16384.f * (float)accA[nj][2] + 128.f * (float)accB[nj][2]) * invr;
            float im = (16384.f * (float)accA[nj][3] + 128.f * (float)accB[nj][3]) * invi;
            out[(size_t)b * NF + fA + 8] = sqrtf(re * re + im * im);
        }
    }
}

// ---------------------------------------------------------------------------
extern "C" void kernel_launch(void* const* d_in, const int* in_sizes, int n_in,
                              void* d_out, int out_size) {
    const float* x    = (const float*)d_in[0];
    const float* wcos = (const float*)d_in[1];
    const float* wsin = (const float*)d_in[2];
    const float* kr   = (const float*)d_in[3];
    const float* ki   = (const float*)d_in[4];
    float* out = (float*)d_out;

    static int smem_set = 0;
    if (!smem_set) {
        cudaFuncSetAttribute(k3_cqt, cudaFuncAttributeMaxDynamicSharedMemorySize, K3_SMEM);
        smem_set = 1;
    }

    kx_quant<<<(XPAD / 4 + 255) / 256, 256>>>(x);
    k1_combine<<<dim3(16, 3, KSPLIT), 256>>>(kr, ki, wcos, wsin);
    k2_quant<<<NROW, 256>>>();
    k3_cqt<<<256, K3T, K3_SMEM>>>(out);
}

// round 9
// speedup vs baseline: 1.5202x; 1.5202x over previous
#include <cuda_runtime.h>
#include <cuda_bf16.h>
#include <cstdint>

#define NF      16381
#define NBINS   84
#define KLEN    1025
#define FFTLEN  2048
#define HOP     512
#define NSAMP   8388608
#define XPAD    (NSAMP + 2048)

typedef unsigned long long ull;

__device__ __forceinline__ ull pk2(float a, float b) {
    ull r; asm("mov.b64 %0, {%1, %2};" : "=l"(r) : "f"(a), "f"(b)); return r;
}
__device__ __forceinline__ ull ffma2(ull a, ull b, ull c) {
    ull d; asm("fma.rn.f32x2 %0, %1, %2, %3;" : "=l"(d) : "l"(a), "l"(b), "l"(c)); return d;
}
__device__ __forceinline__ float2 upk2(ull v) {
    float2 f; asm("mov.b64 {%0, %1}, %2;" : "=f"(f.x), "=f"(f.y) : "l"(v)); return f;
}
__device__ __forceinline__ uint32_t smem_u32(const void* p) {
    uint32_t a; asm("{ .reg .u64 t; cvta.to.shared.u64 t, %1; cvt.u32.u64 %0, t; }" : "=r"(a) : "l"(p));
    return a;
}

// ---------------- scratch globals ----------------
#define KSPLIT 8
__device__ float2 g_part[KSPLIT][96 * FFTLEN];       // k1 partials [z][b*2048+n]
__device__ __nv_bfloat16 g_xhi[XPAD];
__device__ __nv_bfloat16 g_xlo[XPAD];

#define NROW 192                                     // B rows: 168 used (84 bins x re/im)
__device__ __nv_bfloat16 g_B[2][NROW * FFTLEN];      // [hi/lo][row][k] row-major

// ---------------------------------------------------------------------------
// k1: combined kernels Cmb[b,n] = (kr@wc - ki@ws, kr@ws + ki@wc)
// grid(16, 3, 8) x 256.  Thread: 4 bins x 4 n.
// ---------------------------------------------------------------------------
__global__ __launch_bounds__(256) void k1_combine(const float* __restrict__ kr,
                                                  const float* __restrict__ ki,
                                                  const float* __restrict__ wc,
                                                  const float* __restrict__ ws) {
    int tid = threadIdx.x;
    int nt = tid & 31, bt = tid >> 5;
    int b0 = blockIdx.y * 32 + bt * 4;
    if (b0 >= NBINS) return;
    int n0 = blockIdx.x * 128 + nt * 4;
    int z = blockIdx.z;
    int k = z * 128;
    int kend = (z == KSPLIT - 1) ? KLEN : k + 128;

    const float* krp = kr + (size_t)b0 * KLEN;
    const float* kip = ki + (size_t)b0 * KLEN;

    ull accr[4][2], acci[4][2];
#pragma unroll
    for (int i = 0; i < 4; i++)
#pragma unroll
        for (int j = 0; j < 2; j++) { accr[i][j] = 0ull; acci[i][j] = 0ull; }

#pragma unroll 4
    for (; k < kend; k++) {
        ulonglong2 c2 = *(const ulonglong2*)(wc + (size_t)k * FFTLEN + n0);
        ulonglong2 s2 = *(const ulonglong2*)(ws + (size_t)k * FFTLEN + n0);
        ull cp[2] = {c2.x, c2.y};
        ull sp[2] = {s2.x, s2.y};
#pragma unroll
        for (int i = 0; i < 4; i++) {
            float r  = __ldg(krp + (size_t)i * KLEN + k);
            float im = __ldg(kip + (size_t)i * KLEN + k);
            ull krd = pk2(r, r), kin = pk2(-im, -im), kp = pk2(im, im);
#pragma unroll
            for (int j = 0; j < 2; j++) {
                accr[i][j] = ffma2(krd, cp[j], accr[i][j]);
                accr[i][j] = ffma2(kin, sp[j], accr[i][j]);
                acci[i][j] = ffma2(krd, sp[j], acci[i][j]);
                acci[i][j] = ffma2(kp,  cp[j], acci[i][j]);
            }
        }
    }

#pragma unroll
    for (int i = 0; i < 4; i++)
#pragma unroll
        for (int j = 0; j < 2; j++) {
            float2 r = upk2(accr[i][j]);
            float2 m = upk2(acci[i][j]);
            float4 v = make_float4(r.x, m.x, r.y, m.y);
            *(float4*)&g_part[z][(size_t)(b0 + i) * FFTLEN + n0 + 2 * j] = v;
        }
}

// ---------------------------------------------------------------------------
// kx: split x into bf16 hi/lo with zero pad tail
// ---------------------------------------------------------------------------
__global__ __launch_bounds__(256) void kx_split(const float* __restrict__ x) {
    size_t base = ((size_t)blockIdx.x * 256 + threadIdx.x) * 4;
    if (base >= XPAD) return;
    float4 v = make_float4(0.f, 0.f, 0.f, 0.f);
    if (base + 4 <= NSAMP) v = *(const float4*)(x + base);
    float vs[4] = {v.x, v.y, v.z, v.w};
    ushort4 h, l;
    unsigned short* hp = &h.x;
    unsigned short* lp = &l.x;
#pragma unroll
    for (int t = 0; t < 4; t++) {
        __nv_bfloat16 bh = __float2bfloat16(vs[t]);
        __nv_bfloat16 bl = __float2bfloat16(vs[t] - __bfloat162float(bh));
        hp[t] = __bfloat16_as_ushort(bh);
        lp[t] = __bfloat16_as_ushort(bl);
    }
    *(ushort4*)(g_xhi + base) = h;
    *(ushort4*)(g_xlo + base) = l;
}

// ---------------------------------------------------------------------------
// k2: fold k1 partials, hi/lo split -> g_B[img][row][k].  row 2b = Cr, 2b+1 = Ci.
// ---------------------------------------------------------------------------
__global__ __launch_bounds__(256) void k2_pack() {
    int gid = blockIdx.x * 256 + threadIdx.x;
    int j = gid >> 8;
    int n0 = (gid & 255) << 3;
    float v[8];
#pragma unroll
    for (int t = 0; t < 8; t++) v[t] = 0.f;
    if (j < 2 * NBINS) {
        int b = j >> 1, im = j & 1;
#pragma unroll
        for (int z = 0; z < KSPLIT; z++) {
            const float2* p = &g_part[z][(size_t)b * FFTLEN + n0];
#pragma unroll
            for (int t = 0; t < 8; t++) v[t] += im ? p[t].y : p[t].x;
        }
    }
    ushort4 hq[2], lq[2];
    unsigned short* hp = &hq[0].x;
    unsigned short* lp = &lq[0].x;
#pragma unroll
    for (int t = 0; t < 8; t++) {
        __nv_bfloat16 bh = __float2bfloat16(v[t]);
        __nv_bfloat16 bl = __float2bfloat16(v[t] - __bfloat162float(bh));
        hp[t] = __bfloat16_as_ushort(bh);
        lp[t] = __bfloat16_as_ushort(bl);
    }
    *(uint4*)&g_B[0][(size_t)j * FFTLEN + n0] = *(uint4*)&hq[0];
    *(uint4*)&g_B[1][(size_t)j * FFTLEN + n0] = *(uint4*)&lq[0];
}

// ---------------------------------------------------------------------------
// k3: warp bf16 HMMA GEMM, 4-stage cp.async ring, PAIRED chunks:
// one wait+barrier+refill per 2 chunks; frag double-buffering spans the pair.
// CTA: 64 frames x 192 rows, 8 warps (2M x 4N), warp tile 32x48.
// ---------------------------------------------------------------------------
#define K3T 256
#define KCH 32
#define NCHSEG (FFTLEN / KCH)     // 64
#define NCHUNK (3 * NCHSEG)       // 192
#define ROWB 80
#define CTAM 64
#define A_SM (CTAM * ROWB)        // 5120
#define B_SM (NROW * ROWB)        // 15360
#define STAGE (A_SM + B_SM)       // 20480
#define NSTAGE 4
#define K3_SMEM (NSTAGE * STAGE)  // 81920

__device__ __forceinline__ void ldsm4(uint32_t* r, uint32_t addr) {
    asm volatile("ldmatrix.sync.aligned.m8n8.x4.shared.b16 {%0,%1,%2,%3}, [%4];"
                 : "=r"(r[0]), "=r"(r[1]), "=r"(r[2]), "=r"(r[3]) : "r"(addr));
}
__device__ __forceinline__ void hmma(float* d, const uint32_t* a, uint32_t b0, uint32_t b1) {
    asm volatile("mma.sync.aligned.m16n8k16.row.col.f32.bf16.bf16.f32 "
                 "{%0,%1,%2,%3}, {%4,%5,%6,%7}, {%8,%9}, {%0,%1,%2,%3};"
                 : "+f"(d[0]), "+f"(d[1]), "+f"(d[2]), "+f"(d[3])
                 : "r"(a[0]), "r"(a[1]), "r"(a[2]), "r"(a[3]), "r"(b0), "r"(b1));
}
__device__ __forceinline__ void cp16(uint32_t dst, const void* src) {
    asm volatile("cp.async.cg.shared.global [%0], [%1], 16;" :: "r"(dst), "l"(src));
}

__global__ __launch_bounds__(K3T, 2) void k3_cqt(float* __restrict__ out) {
    extern __shared__ __align__(16) char dsm[];
    uint32_t sb = smem_u32(dsm);

    int tid = threadIdx.x;
    int lane = tid & 31, wid = tid >> 5;
    int wm = wid & 1, wn = wid >> 1;
    int f0 = blockIdx.x * CTAM;

    int arow = tid >> 2, aq = tid & 3;

    auto issue = [&](int c) {
        if (c >= NCHUNK) return;
        int s = c & 3;
        int seg = c / NCHSEG;
        int n0 = (c % NCHSEG) * KCH;
        const __nv_bfloat16* xs = (seg == 1) ? g_xlo : g_xhi;
        const __nv_bfloat16* bi = g_B[seg == 2 ? 1 : 0];
        uint32_t ab = sb + s * STAGE;
        cp16(ab + arow * ROWB + aq * 16,
             xs + (size_t)(f0 + arow) * HOP + n0 + aq * 8);
        uint32_t bb = ab + A_SM;
#pragma unroll
        for (int w = 0; w < 3; w++) {
            int u = tid + w * 256;
            int row = u >> 2, q = u & 3;
            cp16(bb + row * ROWB + q * 16,
                 bi + (size_t)row * FFTLEN + n0 + q * 8);
        }
        asm volatile("cp.async.commit_group;" ::: "memory");
    };

    float acc[2][6][4];
#pragma unroll
    for (int mi = 0; mi < 2; mi++)
#pragma unroll
        for (int nj = 0; nj < 6; nj++)
#pragma unroll
            for (int t = 0; t < 4; t++) acc[mi][nj][t] = 0.f;

    int lrow8 = ((lane >> 3) & 1) * 8 + (lane & 7);
    int lkh = (lane >> 4) * 16;
    uint32_t aoff = (wm * 32 + lrow8) * ROWB + lkh;
    uint32_t boff = A_SM + (wn * 48 + lrow8) * ROWB + lkh;

    issue(0); issue(1); issue(2); issue(3);
    asm volatile("cp.async.wait_group 2;" ::: "memory");   // chunks 0,1 arrived
    __syncthreads();

    uint32_t af0[2][4], bf0[3][4], af1[2][4], bf1[3][4];

#define LOAD_FRAGS(A, B, base, hofs)                                        \
    do {                                                                    \
        _Pragma("unroll")                                                   \
        for (int mi = 0; mi < 2; mi++) ldsm4(A[mi], (base) + aoff + mi * 16 * ROWB + (hofs)); \
        _Pragma("unroll")                                                   \
        for (int ni = 0; ni < 3; ni++) ldsm4(B[ni], (base) + boff + ni * 16 * ROWB + (hofs)); \
    } while (0)

#define DO_HMMA(ACC_A, ACC_B)                                               \
    do {                                                                    \
        _Pragma("unroll")                                                   \
        for (int mi = 0; mi < 2; mi++)                                      \
            _Pragma("unroll")                                               \
            for (int nj = 0; nj < 6; nj++) {                                \
                int ni = nj >> 1, half = nj & 1;                            \
                hmma(acc[mi][nj], ACC_A[mi], ACC_B[ni][half], ACC_B[ni][half + 2]); \
            }                                                               \
    } while (0)

    for (int P = 0; P < NCHUNK; P += 2) {
        uint32_t abP = sb + (P & 3) * STAGE;
        uint32_t abQ = sb + ((P + 1) & 3) * STAGE;

        // preload (P, h0)
        LOAD_FRAGS(af0, bf0, abP, 0);
        // step 1: prefetch (P,h1), compute (P,h0)
        LOAD_FRAGS(af1, bf1, abP, 32);
        DO_HMMA(af0, bf0);
        // step 2: prefetch (P+1,h0), compute (P,h1)
        LOAD_FRAGS(af0, bf0, abQ, 0);
        DO_HMMA(af1, bf1);
        // step 3: prefetch (P+1,h1), compute (P+1,h0)
        LOAD_FRAGS(af1, bf1, abQ, 32);
        DO_HMMA(af0, bf0);
        // step 4: compute (P+1,h1)
        DO_HMMA(af1, bf1);

        if (P + 2 < NCHUNK) {
            asm volatile("cp.async.wait_group 0;" ::: "memory");  // P+2,P+3 arrived
            __syncthreads();                                       // visibility + refill safety
            issue(P + 4);
            issue(P + 5);
        }
    }

    // epilogue: magnitude + store
#pragma unroll
    for (int mi = 0; mi < 2; mi++)
#pragma unroll
        for (int nj = 0; nj < 6; nj++) {
            int n_even = wn * 48 + nj * 8 + (lane & 3) * 2;
            int b = n_even >> 1;
            int fA = f0 + wm * 32 + mi * 16 + (lane >> 2);
            if (b < NBINS) {
                if (fA < NF) {
                    float re = acc[mi][nj][0], im = acc[mi][nj][1];
                    out[(size_t)b * NF + fA] = sqrtf(re * re + im * im);
                }
                if (fA + 8 < NF) {
                    float re = acc[mi][nj][2], im = acc[mi][nj][3];
                    out[(size_t)b * NF + fA + 8] = sqrtf(re * re + im * im);
                }
            }
        }
}

// ---------------------------------------------------------------------------
extern "C" void kernel_launch(void* const* d_in, const int* in_sizes, int n_in,
                              void* d_out, int out_size) {
    const float* x    = (const float*)d_in[0];
    const float* wcos = (const float*)d_in[1];
    const float* wsin = (const float*)d_in[2];
    const float* kr   = (const float*)d_in[3];
    const float* ki   = (const float*)d_in[4];
    float* out = (float*)d_out;

    static int smem_set = 0;
    if (!smem_set) {
        cudaFuncSetAttribute(k3_cqt, cudaFuncAttributeMaxDynamicSharedMemorySize, K3_SMEM);
        smem_set = 1;
    }

    kx_split<<<(XPAD / 4 + 255) / 256, 256>>>(x);
    k1_combine<<<dim3(16, 3, KSPLIT), 256>>>(kr, ki, wcos, wsin);
    k2_pack<<<192, 256>>>();
    k3_cqt<<<256, K3T, K3_SMEM>>>(out);
}

// round 10
// speedup vs baseline: 2.4014x; 1.5797x over previous
#include <cuda_runtime.h>
#include <cuda_bf16.h>
#include <cstdint>

#define NF      16381
#define NBINS   84
#define KLEN    1025
#define FFTLEN  2048
#define HOP     512
#define NSAMP   8388608
#define XPAD    (NSAMP + 2048)

typedef unsigned long long ull;

__device__ __forceinline__ uint32_t smem_u32(const void* p) {
    uint32_t a; asm("{ .reg .u64 t; cvta.to.shared.u64 t, %1; cvt.u32.u64 %0, t; }" : "=r"(a) : "l"(p));
    return a;
}

// ---------------- scratch globals ----------------
__device__ __nv_bfloat16 g_xhi[XPAD];
__device__ __nv_bfloat16 g_xlo[XPAD];

#define NROW 192                                     // 168 used (84 bins x re/im)
__device__ __nv_bfloat16 g_B[2][NROW * FFTLEN];      // [hi/lo][row][k] row-major

// ---------------------------------------------------------------------------
// kx: split x into bf16 hi/lo with zero pad tail
// ---------------------------------------------------------------------------
__global__ __launch_bounds__(256) void kx_split(const float* __restrict__ x) {
    size_t base = ((size_t)blockIdx.x * 256 + threadIdx.x) * 4;
    if (base >= XPAD) return;
    float4 v = make_float4(0.f, 0.f, 0.f, 0.f);
    if (base + 4 <= NSAMP) v = *(const float4*)(x + base);
    float vs[4] = {v.x, v.y, v.z, v.w};
    ushort4 h, l;
    unsigned short* hp = &h.x;
    unsigned short* lp = &l.x;
#pragma unroll
    for (int t = 0; t < 4; t++) {
        __nv_bfloat16 bh = __float2bfloat16(vs[t]);
        __nv_bfloat16 bl = __float2bfloat16(vs[t] - __bfloat162float(bh));
        hp[t] = __bfloat16_as_ushort(bh);
        lp[t] = __bfloat16_as_ushort(bl);
    }
    *(ushort4*)(g_xhi + base) = h;
    *(ushort4*)(g_xlo + base) = l;
}

// ---------------------------------------------------------------------------
// kfft: combined kernels via inverse DFT.
//   C[b,n] = sum_k (kr[b,k] + j*ki[b,k]) * exp(+j*2*pi*k*n/2048)
// One CTA per bin row; 2048-pt radix-2 complex FFT in smem (input bit-reversed,
// DIT, twiddle sign +). Then hi/lo bf16 split into g_B rows 2b (Re), 2b+1 (Im).
// Blocks b >= 84 write zero rows (pad to NROW).
// ---------------------------------------------------------------------------
__global__ __launch_bounds__(256) void kfft(const float* __restrict__ kr,
                                            const float* __restrict__ ki) {
    __shared__ float2 a[FFTLEN];
    int b = blockIdx.x;          // 0..95
    int tid = threadIdx.x;

    if (b < NBINS) {
        // load zero-padded kernel row in bit-reversed order
        for (int k = tid; k < FFTLEN; k += 256) {
            float2 v = make_float2(0.f, 0.f);
            if (k < KLEN) v = make_float2(kr[(size_t)b * KLEN + k],
                                          ki[(size_t)b * KLEN + k]);
            a[__brev((unsigned)k) >> 21] = v;
        }
        __syncthreads();

        // 11 radix-2 DIT stages, twiddle exp(+j*2*pi*pos/m)
        for (int s = 1; s <= 11; s++) {
            int mh = 1 << (s - 1);
            float angstep = 6.283185307179586f / (float)(mh << 1);
            for (int t = tid; t < FFTLEN / 2; t += 256) {
                int pos = t & (mh - 1);
                int grp = t >> (s - 1);
                int i1 = (grp << s) + pos;
                int i2 = i1 + mh;
                float sw, cw;
                sincosf(angstep * (float)pos, &sw, &cw);
                float2 u = a[i1], w = a[i2];
                float2 v = make_float2(w.x * cw - w.y * sw,
                                       w.x * sw + w.y * cw);
                a[i1] = make_float2(u.x + v.x, u.y + v.y);
                a[i2] = make_float2(u.x - v.x, u.y - v.y);
            }
            __syncthreads();
        }
    }

    // hi/lo split -> g_B rows 2b (Cr), 2b+1 (Ci); zero rows for b >= NBINS
    for (int n = tid; n < FFTLEN; n += 256) {
        float cr = 0.f, ci = 0.f;
        if (b < NBINS) { cr = a[n].x; ci = a[n].y; }
        __nv_bfloat16 crh = __float2bfloat16(cr);
        __nv_bfloat16 crl = __float2bfloat16(cr - __bfloat162float(crh));
        __nv_bfloat16 cih = __float2bfloat16(ci);
        __nv_bfloat16 cil = __float2bfloat16(ci - __bfloat162float(cih));
        g_B[0][(size_t)(2 * b) * FFTLEN + n]     = crh;
        g_B[1][(size_t)(2 * b) * FFTLEN + n]     = crl;
        g_B[0][(size_t)(2 * b + 1) * FFTLEN + n] = cih;
        g_B[1][(size_t)(2 * b + 1) * FFTLEN + n] = cil;
    }
}

// ---------------------------------------------------------------------------
// k3: warp bf16 HMMA GEMM (exact R7 config: 4-stage ring, frag double-buffer,
// one wait+sync per chunk). CTA: 64 frames x 192 rows, 8 warps (2M x 4N),
// warp tile 32x48, 80-byte padded smem rows.
// ---------------------------------------------------------------------------
#define K3T 256
#define KCH 32
#define NCHSEG (FFTLEN / KCH)     // 64
#define NCHUNK (3 * NCHSEG)       // 192
#define ROWB 80
#define CTAM 64
#define A_SM (CTAM * ROWB)        // 5120
#define B_SM (NROW * ROWB)        // 15360
#define STAGE (A_SM + B_SM)       // 20480
#define NSTAGE 4
#define K3_SMEM (NSTAGE * STAGE)  // 81920

__device__ __forceinline__ void ldsm4(uint32_t* r, uint32_t addr) {
    asm volatile("ldmatrix.sync.aligned.m8n8.x4.shared.b16 {%0,%1,%2,%3}, [%4];"
                 : "=r"(r[0]), "=r"(r[1]), "=r"(r[2]), "=r"(r[3]) : "r"(addr));
}
__device__ __forceinline__ void hmma(float* d, const uint32_t* a, uint32_t b0, uint32_t b1) {
    asm volatile("mma.sync.aligned.m16n8k16.row.col.f32.bf16.bf16.f32 "
                 "{%0,%1,%2,%3}, {%4,%5,%6,%7}, {%8,%9}, {%0,%1,%2,%3};"
                 : "+f"(d[0]), "+f"(d[1]), "+f"(d[2]), "+f"(d[3])
                 : "r"(a[0]), "r"(a[1]), "r"(a[2]), "r"(a[3]), "r"(b0), "r"(b1));
}
__device__ __forceinline__ void cp16(uint32_t dst, const void* src) {
    asm volatile("cp.async.cg.shared.global [%0], [%1], 16;" :: "r"(dst), "l"(src));
}

__global__ __launch_bounds__(K3T, 2) void k3_cqt(float* __restrict__ out) {
    extern __shared__ __align__(16) char dsm[];
    uint32_t sb = smem_u32(dsm);

    int tid = threadIdx.x;
    int lane = tid & 31, wid = tid >> 5;
    int wm = wid & 1, wn = wid >> 1;
    int f0 = blockIdx.x * CTAM;

    int arow = tid >> 2, aq = tid & 3;

    auto issue = [&](int c) {
        int s = c & 3;
        int seg = c / NCHSEG;
        int n0 = (c % NCHSEG) * KCH;
        const __nv_bfloat16* xs = (seg == 1) ? g_xlo : g_xhi;
        const __nv_bfloat16* bi = g_B[seg == 2 ? 1 : 0];
        uint32_t ab = sb + s * STAGE;
        cp16(ab + arow * ROWB + aq * 16,
             xs + (size_t)(f0 + arow) * HOP + n0 + aq * 8);
        uint32_t bb = ab + A_SM;
#pragma unroll
        for (int w = 0; w < 3; w++) {
            int u = tid + w * 256;
            int row = u >> 2, q = u & 3;
            cp16(bb + row * ROWB + q * 16,
                 bi + (size_t)row * FFTLEN + n0 + q * 8);
        }
        asm volatile("cp.async.commit_group;" ::: "memory");
    };

    float acc[2][6][4];
#pragma unroll
    for (int mi = 0; mi < 2; mi++)
#pragma unroll
        for (int nj = 0; nj < 6; nj++)
#pragma unroll
            for (int t = 0; t < 4; t++) acc[mi][nj][t] = 0.f;

    int lrow8 = ((lane >> 3) & 1) * 8 + (lane & 7);
    int lkh = (lane >> 4) * 16;
    uint32_t aoff = (wm * 32 + lrow8) * ROWB + lkh;
    uint32_t boff = A_SM + (wn * 48 + lrow8) * ROWB + lkh;

    issue(0); issue(1); issue(2); issue(3);
    asm volatile("cp.async.wait_group 2;" ::: "memory");
    __syncthreads();

    uint32_t af0[2][4], bf0[3][4], af1[2][4], bf1[3][4];
    {
        uint32_t ab = sb;  // stage 0, h0
#pragma unroll
        for (int mi = 0; mi < 2; mi++) ldsm4(af0[mi], ab + aoff + mi * 16 * ROWB);
#pragma unroll
        for (int ni = 0; ni < 3; ni++) ldsm4(bf0[ni], ab + boff + ni * 16 * ROWB);
    }

    for (int c = 0; c < NCHUNK; c++) {
        uint32_t ab  = sb + (c & 3) * STAGE;
        uint32_t ab1 = sb + ((c + 1) & 3) * STAGE;

        // h0: prefetch (c,h1), compute buf0
#pragma unroll
        for (int mi = 0; mi < 2; mi++) ldsm4(af1[mi], ab + aoff + mi * 16 * ROWB + 32);
#pragma unroll
        for (int ni = 0; ni < 3; ni++) ldsm4(bf1[ni], ab + boff + ni * 16 * ROWB + 32);
#pragma unroll
        for (int mi = 0; mi < 2; mi++)
#pragma unroll
            for (int nj = 0; nj < 6; nj++) {
                int ni = nj >> 1, half = nj & 1;
                hmma(acc[mi][nj], af0[mi], bf0[ni][half], bf0[ni][half + 2]);
            }

        // h1: prefetch (c+1,h0), compute buf1
        if (c + 1 < NCHUNK) {
#pragma unroll
            for (int mi = 0; mi < 2; mi++) ldsm4(af0[mi], ab1 + aoff + mi * 16 * ROWB);
#pragma unroll
            for (int ni = 0; ni < 3; ni++) ldsm4(bf0[ni], ab1 + boff + ni * 16 * ROWB);
        }
#pragma unroll
        for (int mi = 0; mi < 2; mi++)
#pragma unroll
            for (int nj = 0; nj < 6; nj++) {
                int ni = nj >> 1, half = nj & 1;
                hmma(acc[mi][nj], af1[mi], bf1[ni][half], bf1[ni][half + 2]);
            }

        if (c + 4 < NCHUNK) {
            asm volatile("cp.async.wait_group 1;" ::: "memory");
            __syncthreads();
            issue(c + 4);
        } else {
            asm volatile("cp.async.wait_group 0;" ::: "memory");
            __syncthreads();
        }
    }

    // epilogue: magnitude + store
#pragma unroll
    for (int mi = 0; mi < 2; mi++)
#pragma unroll
        for (int nj = 0; nj < 6; nj++) {
            int n_even = wn * 48 + nj * 8 + (lane & 3) * 2;
            int b = n_even >> 1;
            int fA = f0 + wm * 32 + mi * 16 + (lane >> 2);
            if (b < NBINS) {
                if (fA < NF) {
                    float re = acc[mi][nj][0], im = acc[mi][nj][1];
                    out[(size_t)b * NF + fA] = sqrtf(re * re + im * im);
                }
                if (fA + 8 < NF) {
                    float re = acc[mi][nj][2], im = acc[mi][nj][3];
                    out[(size_t)b * NF + fA + 8] = sqrtf(re * re + im * im);
                }
            }
        }
}

// ---------------------------------------------------------------------------
extern "C" void kernel_launch(void* const* d_in, const int* in_sizes, int n_in,
                              void* d_out, int out_size) {
    const float* x    = (const float*)d_in[0];
    const float* kr   = (const float*)d_in[3];
    const float* ki   = (const float*)d_in[4];
    float* out = (float*)d_out;

    static int smem_set = 0;
    if (!smem_set) {
        cudaFuncSetAttribute(k3_cqt, cudaFuncAttributeMaxDynamicSharedMemorySize, K3_SMEM);
        smem_set = 1;
    }

    kx_split<<<(XPAD / 4 + 255) / 256, 256>>>(x);
    kfft<<<96, 256>>>(kr, ki);
    k3_cqt<<<256, K3T, K3_SMEM>>>(out);
}